// round 4
// baseline (speedup 1.0000x reference)
#include <cuda_runtime.h>

// ---------------------------------------------------------------------------
// LBP histogram kernel, GB300 sm_103a — round 3
// img: [16,3,1024,1024] fp32  ->  out: [1,256] fp32 standardized histogram
// Single fused kernel: float4 lanes (128-col strips), swizzled per-thread byte
// histograms, dynamic warp ticketing, last-block finalize.
// ---------------------------------------------------------------------------

#define IMG_H 1024
#define IMG_W 1024
#define HW (IMG_H * IMG_W)

#define THREADS 256
#define BLOCKS 444                 // 148 SMs * 3 blocks (64 KB smem each)
#define CHUNK 32                   // rows per task
#define N_TASKS (16 * 8 * 32)      // 16 imgs * 8 strips(128 col) * 32 chunks

__device__ unsigned int g_count[256];
__device__ unsigned int g_ticket;
__device__ unsigned int g_done;

struct Row { float4 g; float l, r; };

__device__ __forceinline__ float gray1(float r, float g, float b) {
    return fmaf(0.114f, b, fmaf(0.587f, g, 0.299f * r));
}

// Load one gray row (4 px/lane) for a 128-column strip, halo cols + zero pad.
// Single merged halo path (lanes 0 and 31 only), predication-friendly.
__device__ __forceinline__ Row load_row4(const float* __restrict__ base,
                                         int r, int rmax, int c0, int lane) {
    Row o;
    o.g = make_float4(0.f, 0.f, 0.f, 0.f);
    float h = 0.f;
    if ((unsigned)r < (unsigned)IMG_H && r <= rmax) {
        const float* q = base + (size_t)r * IMG_W;
        const float4* p = (const float4*)(q + c0) + lane;
        float4 cr = __ldcs(p);
        float4 cg = __ldcs(p + (HW >> 2));
        float4 cb = __ldcs(p + (HW >> 1));
        o.g.x = gray1(cr.x, cg.x, cb.x);
        o.g.y = gray1(cr.y, cg.y, cb.y);
        o.g.z = gray1(cr.z, cg.z, cb.z);
        o.g.w = gray1(cr.w, cg.w, cb.w);
        // merged halo: lane0 -> col c0-1, lane31 -> col c0+128
        int hc = (lane == 0) ? (c0 - 1) : (c0 + 128);
        if (((lane == 0) | (lane == 31)) && (unsigned)hc < (unsigned)IMG_W)
            h = gray1(q[hc], q[hc + HW], q[hc + 2 * HW]);
    }
    float sl = __shfl_up_sync(0xffffffffu, o.g.w, 1);
    float sr = __shfl_down_sync(0xffffffffu, o.g.x, 1);
    o.l = (lane == 0) ? h : sl;
    o.r = (lane == 31) ? h : sr;
    return o;
}

__device__ __forceinline__ void upd(unsigned char* __restrict__ hist, int tid,
                                    float c, float tl, float t, float tr,
                                    float l, float rr, float bl, float b,
                                    float br) {
    unsigned code;
    code  = (tr >= c) ?   1u : 0u;   // top-right
    code |= (rr >= c) ?   2u : 0u;   // right
    code |= (br >= c) ?   4u : 0u;   // bottom-right
    code |= (b  >= c) ?   8u : 0u;   // bottom
    code |= (bl >= c) ?  16u : 0u;   // bottom-left
    code |= (l  >= c) ?  32u : 0u;   // left
    code |= (tl >= c) ?  64u : 0u;   // top-left
    code |= (t  >= c) ? 128u : 0u;   // top
    // swizzle: different codes in a lane-quad -> different banks; equal codes
    // -> same word, distinct bytes (merge). Thread-exclusive per code block.
    hist[(code << 8) + ((tid + (code << 2)) & 255)]++;
}

extern "C" __global__ void __launch_bounds__(THREADS, 3)
lbp_main(const float* __restrict__ img, float* __restrict__ out) {
    extern __shared__ unsigned char hist[];   // 64 KB
    __shared__ float sh[256];
    __shared__ int s_last;
    const int tid = threadIdx.x;
    const int lane = tid & 31;

    uint4* h4 = (uint4*)hist;
#pragma unroll
    for (int i = 0; i < 16; i++)
        h4[tid + i * THREADS] = make_uint4(0u, 0u, 0u, 0u);
    __syncthreads();

    for (;;) {
        unsigned t;
        if (lane == 0) t = atomicAdd(&g_ticket, 1u);
        t = __shfl_sync(0xffffffffu, t, 0);
        if (t >= N_TASKS) break;

        const int chunk = t & 31;            // row chunk
        const int strip = (t >> 5) & 7;      // 128-col strip
        const int b = t >> 8;                // image
        const int c0 = strip << 7;
        const int r0 = chunk * CHUNK;
        const int rmax = r0 + CHUNK;         // deepest row actually needed
        const float* base = img + (size_t)b * 3 * HW;

        // 5-row register pipeline (3-iteration load lookahead)
        Row top = load_row4(base, r0 - 1, rmax, c0, lane);
        Row mid = load_row4(base, r0,     rmax, c0, lane);
        Row bot = load_row4(base, r0 + 1, rmax, c0, lane);
        Row n1  = load_row4(base, r0 + 2, rmax, c0, lane);
        Row n2  = load_row4(base, r0 + 3, rmax, c0, lane);

#pragma unroll 4
        for (int r = r0; r < r0 + CHUNK; r++) {
            Row n3 = load_row4(base, r + 4, rmax, c0, lane);

            upd(hist, tid, mid.g.x, top.l,   top.g.x, top.g.y,
                mid.l,   mid.g.y, bot.l,   bot.g.x, bot.g.y);
            upd(hist, tid, mid.g.y, top.g.x, top.g.y, top.g.z,
                mid.g.x, mid.g.z, bot.g.x, bot.g.y, bot.g.z);
            upd(hist, tid, mid.g.z, top.g.y, top.g.z, top.g.w,
                mid.g.y, mid.g.w, bot.g.y, bot.g.z, bot.g.w);
            upd(hist, tid, mid.g.w, top.g.z, top.g.w, top.r,
                mid.g.z, mid.r,   bot.g.z, bot.g.w, bot.r);

            top = mid; mid = bot; bot = n1; n1 = n2; n2 = n3;
        }
    }
    __syncthreads();

    // Block reduction: thread tid sums code block tid (64 words, rotated
    // start -> conflict-free). Swizzle is a per-code bijection of bytes,
    // so block sums are unchanged.
    const unsigned int* h32 = (const unsigned int*)hist;
    unsigned int sum = 0;
    const int wbase = tid << 6;
#pragma unroll 8
    for (int j = 0; j < 64; j++) {
        unsigned int w = h32[wbase + ((tid + j) & 63)];
        sum = __dp4a(w, 0x01010101u, sum);
    }
    atomicAdd(&g_count[tid], sum);

    // ---- last-block finalize (fused standardization) ----
    __threadfence();
    if (tid == 0) {
        unsigned d = atomicAdd(&g_done, 1u);
        s_last = (d == BLOCKS - 1);
    }
    __syncthreads();
    if (!s_last) return;

    // read-and-zero counters so every graph replay starts clean
    float h = (float)atomicExch(&g_count[tid], 0u);

    sh[tid] = h;
    __syncthreads();
    for (int s = 128; s > 0; s >>= 1) {
        if (tid < s) sh[tid] += sh[tid + s];
        __syncthreads();
    }
    const float mean = sh[0] * (1.0f / 256.0f);
    __syncthreads();

    const float d = h - mean;
    sh[tid] = d * d;
    __syncthreads();
    for (int s = 128; s > 0; s >>= 1) {
        if (tid < s) sh[tid] += sh[tid + s];
        __syncthreads();
    }
    const float stdv = sqrtf(sh[0] * (1.0f / 255.0f));   // ddof = 1
    out[tid] = d / stdv;

    if (tid == 0) {
        g_ticket = 0u;   // reset work queue for next replay
        g_done = 0u;
    }
}

extern "C" void kernel_launch(void* const* d_in, const int* in_sizes, int n_in,
                              void* d_out, int out_size) {
    (void)in_sizes; (void)n_in; (void)out_size;
    const float* img = (const float*)d_in[0];
    float* out = (float*)d_out;

    cudaFuncSetAttribute(lbp_main, cudaFuncAttributeMaxDynamicSharedMemorySize,
                         65536);
    lbp_main<<<BLOCKS, THREADS, 65536>>>(img, out);
}